// round 13
// baseline (speedup 1.0000x reference)
#include <cuda_runtime.h>
#include <cuda_fp16.h>
#include <cstdint>

#define B_   4
#define T_   2048
#define C_   1024
#define H_   16
#define D_   64
#define M_   (B_*T_)      /* 8192 */
#define N1_  (3*C_)       /* 3072 */

// ---------------- scratch (device globals) -------------------------------------
__device__ __half g_xh   [M_*C_];
__device__ __half g_wkqvT[N1_*C_];   // [N][K] fp16
__device__ __half g_woutT[C_*C_];    // [N][K] fp16
__device__ __half g_q    [M_*C_];
__device__ __half g_k    [M_*C_];
__device__ __half g_v    [M_*C_];
__device__ __half g_att  [M_*C_];

// ---------------- PTX helpers ---------------------------------------------------
__device__ __forceinline__ void cp16(void* smem, const void* gmem) {
    uint32_t s = (uint32_t)__cvta_generic_to_shared(smem);
    asm volatile("cp.async.cg.shared.global [%0], [%1], 16;\n" :: "r"(s), "l"(gmem));
}
__device__ __forceinline__ void cp_commit() {
    asm volatile("cp.async.commit_group;\n");
}
template <int N>
__device__ __forceinline__ void cp_wait() {
    asm volatile("cp.async.wait_group %0;\n" :: "n"(N));
}
__device__ __forceinline__ void ldmx4(uint32_t r[4], uint32_t addr) {
    asm volatile("ldmatrix.sync.aligned.m8n8.x4.shared.b16 {%0,%1,%2,%3}, [%4];"
                 : "=r"(r[0]), "=r"(r[1]), "=r"(r[2]), "=r"(r[3]) : "r"(addr));
}
__device__ __forceinline__ void ldmx4t(uint32_t r[4], uint32_t addr) {
    asm volatile("ldmatrix.sync.aligned.m8n8.x4.trans.shared.b16 {%0,%1,%2,%3}, [%4];"
                 : "=r"(r[0]), "=r"(r[1]), "=r"(r[2]), "=r"(r[3]) : "r"(addr));
}
__device__ __forceinline__ void mma16816(float c[4], const uint32_t a[4],
                                         uint32_t b0, uint32_t b1) {
    asm volatile(
        "mma.sync.aligned.m16n8k16.row.col.f32.f16.f16.f32 "
        "{%0,%1,%2,%3}, {%4,%5,%6,%7}, {%8,%9}, {%0,%1,%2,%3};\n"
        : "+f"(c[0]), "+f"(c[1]), "+f"(c[2]), "+f"(c[3])
        : "r"(a[0]), "r"(a[1]), "r"(a[2]), "r"(a[3]), "r"(b0), "r"(b1));
}
__device__ __forceinline__ void mma16816h(uint32_t c[2], const uint32_t a[4],
                                          uint32_t b0, uint32_t b1) {
    asm volatile(
        "mma.sync.aligned.m16n8k16.row.col.f16.f16.f16.f16 "
        "{%0,%1}, {%2,%3,%4,%5}, {%6,%7}, {%0,%1};\n"
        : "+r"(c[0]), "+r"(c[1])
        : "r"(a[0]), "r"(a[1]), "r"(a[2]), "r"(a[3]), "r"(b0), "r"(b1));
}
__device__ __forceinline__ uint32_t s2u(const void* p) {
    return (uint32_t)__cvta_generic_to_shared(p);
}
__device__ __forceinline__ uint32_t pack_h2(float x, float y) {
    __half2 t = __floats2half2_rn(x, y);
    return *(uint32_t*)&t;
}

// ---------------- fp32 -> fp16 convert (vectorized x4) -------------------------
__global__ void cvt4(const float4* __restrict__ in,
                     __half2* __restrict__ out, int n4) {
    int i = blockIdx.x * blockDim.x + threadIdx.x;
    if (i < n4) {
        float4 v = in[i];
        out[2*i]   = __floats2half2_rn(v.x, v.y);
        out[2*i+1] = __floats2half2_rn(v.z, v.w);
    }
}

// ---------------- fp32 [K][N] -> fp16 transposed [N][K], dual-tensor ------------
// z = 0: W_kqv (N = N1_), z = 1: W_out (N = C_). K = C_ for both.
__global__ void cvt_T2(const float* __restrict__ in0, __half* __restrict__ out0,
                       const float* __restrict__ in1, __half* __restrict__ out1) {
    const int z = blockIdx.z;
    const int N = z ? C_ : N1_;
    if (blockIdx.x * 32 >= N) return;
    const float* in  = z ? in1  : in0;
    __half*      outT = z ? out1 : out0;
    const int K = C_;

    __shared__ float tile[32][33];
    int n0 = blockIdx.x * 32, k0 = blockIdx.y * 32;
    int tx = threadIdx.x & 31, ty = threadIdx.x >> 5;   // 256 thr: ty 0..7
    #pragma unroll
    for (int i = 0; i < 32; i += 8)
        tile[ty + i][tx] = in[(size_t)(k0 + ty + i)*N + n0 + tx];
    __syncthreads();
    #pragma unroll
    for (int i = 0; i < 32; i += 8)
        outT[(size_t)(n0 + ty + i)*K + k0 + tx] = __float2half_rn(tile[tx][ty + i]);
}

// ---------------- fused raw-mma fp16 GEMM: 4-stage ring, paired chunks ----------
// C[M][N] = A[M][K] * Bt[N][K]^T, fp32 accum.
// mode 0: + bias, scatter k/q/v head-major. mode 1: + bias, fp32 out.
#define GBM 128
#define GBN 256
#define GBK 64
#define GSTR 72

struct GStage {
    __half A [GBM*GSTR];
    __half Bn[GBN*GSTR];
};
#define G_SMEM_BYTES (4 * (int)sizeof(GStage))   /* 221184 B */

__global__ void __launch_bounds__(256, 1)
gemm_fused(const __half* __restrict__ Ag, const __half* __restrict__ Bt,
           const float* __restrict__ bias, int K, int Nout, int mode,
           __half* __restrict__ k_out, __half* __restrict__ q_out,
           __half* __restrict__ v_out, float* __restrict__ f_out) {
    extern __shared__ __align__(128) char smem_raw[];
    GStage* stg = reinterpret_cast<GStage*>(smem_raw);

    const int tid  = threadIdx.x;
    const int warp = tid >> 5;
    const int lane = tid & 31;
    const int g    = lane >> 2;
    const int tg   = lane & 3;
    const int bm = blockIdx.y * GBM;
    const int bn = blockIdx.x * GBN;
    const int wm = (warp >> 2) * 64;
    const int wn = (warp & 3) * 64;
    const int NIT = K / GBK;          // 16 (even)

    const int grp = lane >> 3, lr = lane & 7;
    const int rowOffA = ((grp & 1)*8 + lr) * (GSTR*2) + (grp >> 1)*16;
    const int rowOffB = ((grp >> 1)*8 + lr) * (GSTR*2) + (grp & 1)*16;

    auto load_stage = [&](GStage& S, int k0) {
        #pragma unroll
        for (int t = 0; t < 4; t++) {
            int id = tid + 256*t;
            int r = id >> 3, c = (id & 7) * 8;
            cp16(&S.A[r*GSTR + c], &Ag[(size_t)(bm + r)*K + k0 + c]);
        }
        #pragma unroll
        for (int t = 0; t < 8; t++) {
            int id = tid + 256*t;
            int r = id >> 3, c = (id & 7) * 8;
            cp16(&S.Bn[r*GSTR + c], &Bt[(size_t)(bn + r)*K + k0 + c]);
        }
        cp_commit();
    };

    float c[4][8][4];
    #pragma unroll
    for (int i = 0; i < 4; i++)
        #pragma unroll
        for (int j = 0; j < 8; j++)
            c[i][j][0] = c[i][j][1] = c[i][j][2] = c[i][j][3] = 0.f;

    auto compute_stage = [&](GStage& S) {
        const uint32_t baseA = s2u(&S.A[0])  + wm*(GSTR*2) + rowOffA;
        const uint32_t baseB = s2u(&S.Bn[0]) + wn*(GSTR*2) + rowOffB;
        #pragma unroll
        for (int kk = 0; kk < GBK; kk += 16) {
            uint32_t a[4][4], b[4][4];
            #pragma unroll
            for (int mt = 0; mt < 4; mt++)
                ldmx4(a[mt], baseA + mt*16*(GSTR*2) + kk*2);
            #pragma unroll
            for (int nt2 = 0; nt2 < 4; nt2++)
                ldmx4(b[nt2], baseB + nt2*16*(GSTR*2) + kk*2);
            #pragma unroll
            for (int mt = 0; mt < 4; mt++)
                #pragma unroll
                for (int nt = 0; nt < 8; nt++)
                    mma16816(c[mt][nt], a[mt],
                             b[nt >> 1][(nt & 1)*2], b[nt >> 1][(nt & 1)*2 + 1]);
        }
    };

    // prologue: load pair 0 (stages 0,1)
    load_stage(stg[0], 0);
    load_stage(stg[1], GBK);

    for (int it = 0; it < NIT; it += 2) {
        cp_wait<0>();          // this pair's two stages arrived
        __syncthreads();       // all warps done reading the pair being overwritten
        if (it + 2 < NIT) load_stage(stg[(it + 2) & 3], (it + 2) * GBK);
        if (it + 3 < NIT) load_stage(stg[(it + 3) & 3], (it + 3) * GBK);
        compute_stage(stg[it & 3]);
        compute_stage(stg[(it + 1) & 3]);
    }

    #pragma unroll
    for (int nt = 0; nt < 8; nt++) {
        const int n = bn + wn + nt*8 + tg*2;
        const float b0f = bias[n], b1f = bias[n + 1];
        if (mode == 0) {
            const int third = n >> 10;
            const int cc = n & 1023;
            const int hh = cc >> 6, dd = cc & 63;
            __half* dst_arr = (third == 0) ? k_out : (third == 1) ? q_out : v_out;
            const float scale = (third == 1) ? (1.0f/32.0f) : 1.0f;
            #pragma unroll
            for (int mt = 0; mt < 4; mt++) {
                #pragma unroll
                for (int half_ = 0; half_ < 2; half_++) {
                    int m = bm + wm + mt*16 + g + half_*8;
                    int bq = m >> 11, tq = m & (T_ - 1);
                    size_t dst = (((size_t)(bq*H_ + hh))*T_ + tq)*D_ + dd;
                    float v0 = (c[mt][nt][half_*2]     + b0f) * scale;
                    float v1 = (c[mt][nt][half_*2 + 1] + b1f) * scale;
                    *(__half2*)&dst_arr[dst] = __floats2half2_rn(v0, v1);
                }
            }
        } else {
            #pragma unroll
            for (int mt = 0; mt < 4; mt++) {
                #pragma unroll
                for (int half_ = 0; half_ < 2; half_++) {
                    int m = bm + wm + mt*16 + g + half_*8;
                    float2 v;
                    v.x = c[mt][nt][half_*2]     + b0f;
                    v.y = c[mt][nt][half_*2 + 1] + b1f;
                    *(float2*)&f_out[(size_t)m*Nout + n] = v;
                }
            }
        }
    }
}

// ---------------- attention v6 (R12, unchanged) ---------------------------------
#define KST 72
#define ATT_SQ_ELEMS   (128*KST)
#define ATT_SK_ELEMS   (64*KST)
#define ATT_SV_ELEMS   (64*KST)
#define ATT_SMEM_BYTES ((ATT_SQ_ELEMS + 2*ATT_SK_ELEMS + 2*ATT_SV_ELEMS) * 2)

__global__ void __launch_bounds__(256)
attn_kernel(const __half* __restrict__ Qg,
            const __half* __restrict__ Kg,
            const __half* __restrict__ Vg,
            __half* __restrict__ Og) {
    extern __shared__ __align__(16) __half asmem[];
    __half* sQ = asmem;
    __half* sK = sQ + ATT_SQ_ELEMS;
    __half* sV = sK + 2*ATT_SK_ELEMS;

    const int qtile = gridDim.x - 1 - blockIdx.x;   // heavy tiles first
    const int qb  = qtile * 128;
    const int bh  = blockIdx.y;
    const int b   = bh >> 4, h = bh & 15;
    const int tid = threadIdx.x;
    const int warp = tid >> 5, lane = tid & 31;
    const int g  = lane >> 2;
    const int tg = lane & 3;

    const __half* Qb = Qg + (size_t)bh * T_ * D_;
    const __half* Kb = Kg + (size_t)bh * T_ * D_;
    const __half* Vb = Vg + (size_t)bh * T_ * D_;

    #pragma unroll
    for (int t = 0; t < 4; t++) {
        int idx = tid + t*256;
        int r = idx >> 3, c = (idx & 7) * 8;
        *(uint4*)&sQ[r*KST + c] = *(const uint4*)&Qb[(size_t)(qb + r)*D_ + c];
    }
    __syncthreads();

    uint32_t qa[4][4];
    {
        int r0 = warp*16 + g;
        #pragma unroll
        for (int kk = 0; kk < 4; kk++) {
            int cb = kk*16 + tg*2;
            qa[kk][0] = *(uint32_t*)&sQ[r0*KST + cb];
            qa[kk][1] = *(uint32_t*)&sQ[(r0+8)*KST + cb];
            qa[kk][2] = *(uint32_t*)&sQ[r0*KST + cb + 8];
            qa[kk][3] = *(uint32_t*)&sQ[(r0+8)*KST + cb + 8];
        }
    }

    float o[8][4];
    #pragma unroll
    for (int i = 0; i < 8; i++) { o[i][0]=o[i][1]=o[i][2]=o[i][3]=0.f; }
    float m0 = -1e30f, m1 = -1e30f, l0 = 0.f, l1 = 0.f;

    const int ntiles = 2*qtile + 2;
    const int vr = tid >> 3, vc0 = (tid & 7) * 8;

    const uint32_t vlm_off = (uint32_t)(((lane & 15)*KST + ((lane >> 4) << 3)) * 2);

    {
        #pragma unroll
        for (int t = 0; t < 2; t++) {
            int r = vr + t*32;
            cp16(&sK[r*KST + vc0], &Kb[(size_t)r*D_ + vc0]);
            cp16(&sV[r*KST + vc0], &Vb[(size_t)r*D_ + vc0]);
        }
        cp_commit();
    }

    for (int it = 0; it < ntiles; it++) {
        const int kb = it * 64;
        const int stage = it & 1;
        cp_wait<0>();
        __syncthreads();

        const bool pre = (it + 1 < ntiles);
        if (pre) {
            const int kb2 = kb + 64;
            __half* sKn = sK + (stage ^ 1)*ATT_SK_ELEMS;
            __half* sVn = sV + (stage ^ 1)*ATT_SV_ELEMS;
            #pragma unroll
            for (int t = 0; t < 2; t++) {
                int r = vr + t*32;
                cp16(&sKn[r*KST + vc0], &Kb[(size_t)(kb2 + r)*D_ + vc0]);
                cp16(&sVn[r*KST + vc0], &Vb[(size_t)(kb2 + r)*D_ + vc0]);
            }
            cp_commit();
        }

        if (kb <= qb + warp*16 + 15) {
            const __half* sKs = sK + stage*ATT_SK_ELEMS;
            const uint32_t vbase = s2u(sV + stage*ATT_SV_ELEMS) + vlm_off;

            uint32_t sh[8][2];
            #pragma unroll
            for (int nt = 0; nt < 8; nt++) { sh[nt][0] = 0u; sh[nt][1] = 0u; }
            #pragma unroll
            for (int kk = 0; kk < 4; kk++)
                #pragma unroll
                for (int nt = 0; nt < 8; nt++) {
                    uint32_t b0 = *(uint32_t*)&sKs[(nt*8 + g)*KST + kk*16 + tg*2];
                    uint32_t b1 = *(uint32_t*)&sKs[(nt*8 + g)*KST + kk*16 + tg*2 + 8];
                    mma16816h(sh[nt], qa[kk], b0, b1);
                }

            float s[8][4];
            #pragma unroll
            for (int nt = 0; nt < 8; nt++) {
                float2 lo = __half22float2(*(__half2*)&sh[nt][0]);
                float2 hi = __half22float2(*(__half2*)&sh[nt][1]);
                s[nt][0] = lo.x; s[nt][1] = lo.y;
                s[nt][2] = hi.x; s[nt][3] = hi.y;
            }

            if (kb + 63 > qb + warp*16) {
                int qg0 = qb + warp*16 + g;
                #pragma unroll
                for (int nt = 0; nt < 8; nt++) {
                    int kg = kb + nt*8 + tg*2;
                    if (kg     > qg0    ) s[nt][0] = -1e30f;
                    if (kg + 1 > qg0    ) s[nt][1] = -1e30f;
                    if (kg     > qg0 + 8) s[nt][2] = -1e30f;
                    if (kg + 1 > qg0 + 8) s[nt][3] = -1e30f;
                }
            }

            float mx0 = -1e30f, mx1 = -1e30f;
            #pragma unroll
            for (int nt = 0; nt < 8; nt++) {
                mx0 = fmaxf(mx0, fmaxf(s[nt][0], s[nt][1]));
                mx1 = fmaxf(mx1, fmaxf(s[nt][2], s[nt][3]));
            }
            #pragma unroll
            for (int off = 1; off < 4; off <<= 1) {
                mx0 = fmaxf(mx0, __shfl_xor_sync(0xffffffffu, mx0, off));
                mx1 = fmaxf(mx1, __shfl_xor_sync(0xffffffffu, mx1, off));
            }
            float nm0 = fmaxf(m0, mx0), nm1 = fmaxf(m1, mx1);
            float a0 = __expf(m0 - nm0), a1 = __expf(m1 - nm1);
            float sum0 = 0.f, sum1 = 0.f;
            #pragma unroll
            for (int nt = 0; nt < 8; nt++) {
                s[nt][0] = __expf(s[nt][0] - nm0);
                s[nt][1] = __expf(s[nt][1] - nm0);
                s[nt][2] = __expf(s[nt][2] - nm1);
                s[nt][3] = __expf(s[nt][3] - nm1);
                sum0 += s[nt][0] + s[nt][1];
                sum1 += s[nt][2] + s[nt][3];
            }
            #pragma unroll
            for (int off = 1; off < 4; off <<= 1) {
                sum0 += __shfl_xor_sync(0xffffffffu, sum0, off);
                sum1 += __shfl_xor_sync(0xffffffffu, sum1, off);
            }
            l0 = l0*a0 + sum0;  l1 = l1*a1 + sum1;
            m0 = nm0;           m1 = nm1;
            #pragma unroll
            for (int nt = 0; nt < 8; nt++) {
                o[nt][0] *= a0; o[nt][1] *= a0; o[nt][2] *= a1; o[nt][3] *= a1;
            }

            #pragma unroll
            for (int kt = 0; kt < 4; kt++) {
                uint32_t pa[4];
                pa[0] = pack_h2(s[2*kt  ][0], s[2*kt  ][1]);
                pa[1] = pack_h2(s[2*kt  ][2], s[2*kt  ][3]);
                pa[2] = pack_h2(s[2*kt+1][0], s[2*kt+1][1]);
                pa[3] = pack_h2(s[2*kt+1][2], s[2*kt+1][3]);
                #pragma unroll
                for (int ntp = 0; ntp < 8; ntp += 2) {
                    uint32_t bv[4];
                    ldmx4t(bv, vbase + (uint32_t)((kt*16*KST + ntp*8) * 2));
                    mma16816(o[ntp],     pa, bv[0], bv[1]);
                    mma16816(o[ntp + 1], pa, bv[2], bv[3]);
                }
            }
        }
    }

    float inv0 = 1.f / l0, inv1 = 1.f / l1;
    int r0 = qb + warp*16 + g;
    #pragma unroll
    for (int nt = 0; nt < 8; nt++) {
        int dd = nt*8 + tg*2;
        __half2 v0 = __floats2half2_rn(o[nt][0]*inv0, o[nt][1]*inv0);
        __half2 v1 = __floats2half2_rn(o[nt][2]*inv1, o[nt][3]*inv1);
        *(__half2*)&Og[((size_t)b*T_ + r0    )*C_ + h*D_ + dd] = v0;
        *(__half2*)&Og[((size_t)b*T_ + r0 + 8)*C_ + h*D_ + dd] = v1;
    }
}

// ---------------- launch --------------------------------------------------------
extern "C" void kernel_launch(void* const* d_in, const int* in_sizes, int n_in,
                              void* d_out, int out_size) {
    const float* x      = (const float*)d_in[0];
    const float* W_kqv  = (const float*)d_in[1];
    const float* b_kqv  = (const float*)d_in[2];
    const float* W_out  = (const float*)d_in[3];
    const float* b_out  = (const float*)d_in[4];
    float*       out    = (float*)d_out;

    __half *p_xh, *p_wkT, *p_woT, *p_q, *p_k, *p_v, *p_att;
    cudaGetSymbolAddress((void**)&p_xh,  g_xh);
    cudaGetSymbolAddress((void**)&p_wkT, g_wkqvT);
    cudaGetSymbolAddress((void**)&p_woT, g_woutT);
    cudaGetSymbolAddress((void**)&p_q,   g_q);
    cudaGetSymbolAddress((void**)&p_k,   g_k);
    cudaGetSymbolAddress((void**)&p_v,   g_v);
    cudaGetSymbolAddress((void**)&p_att, g_att);

    cudaFuncSetAttribute(gemm_fused,
                         cudaFuncAttributeMaxDynamicSharedMemorySize, G_SMEM_BYTES);
    cudaFuncSetAttribute(attn_kernel,
                         cudaFuncAttributeMaxDynamicSharedMemorySize, ATT_SMEM_BYTES);

    // 1) converts (x; both weight transposes in one launch)
    cvt4<<<(M_*C_/4 + 255)/256, 256>>>((const float4*)x, (__half2*)p_xh, M_*C_/4);
    {
        dim3 gz(N1_/32, C_/32, 2);
        cvt_T2<<<gz, 256>>>(W_kqv, p_wkT, W_out, p_woT);
    }

    // 2) kqv GEMM + fused bias/scatter
    {
        dim3 grid(N1_/GBN, M_/GBM);
        gemm_fused<<<grid, 256, G_SMEM_BYTES>>>(p_xh, p_wkT, b_kqv, C_, N1_, 0,
                                                p_k, p_q, p_v, nullptr);
    }

    // 3) attention
    {
        dim3 grid(T_/128, B_*H_);
        attn_kernel<<<grid, 256, ATT_SMEM_BYTES>>>(p_q, p_k, p_v, p_att);
    }

    // 4) output projection + fused bias -> d_out
    {
        dim3 grid(C_/GBN, M_/GBM);
        gemm_fused<<<grid, 256, G_SMEM_BYTES>>>(p_att, p_woT, b_out, C_, C_, 1,
                                                nullptr, nullptr, nullptr, out);
    }

    (void)in_sizes; (void)n_in; (void)out_size;
}

// round 14
// speedup vs baseline: 1.0141x; 1.0141x over previous
#include <cuda_runtime.h>
#include <cuda_fp16.h>
#include <cstdint>

#define B_   4
#define T_   2048
#define C_   1024
#define H_   16
#define D_   64
#define M_   (B_*T_)      /* 8192 */
#define N1_  (3*C_)       /* 3072 */

// ---------------- scratch (device globals) -------------------------------------
__device__ __half g_xh   [M_*C_];
__device__ __half g_wkqvT[N1_*C_];   // [N][K] fp16
__device__ __half g_woutT[C_*C_];    // [N][K] fp16
__device__ __half g_q    [M_*C_];
__device__ __half g_k    [M_*C_];
__device__ __half g_v    [M_*C_];
__device__ __half g_att  [M_*C_];

// ---------------- PTX helpers ---------------------------------------------------
__device__ __forceinline__ void cp16(void* smem, const void* gmem) {
    uint32_t s = (uint32_t)__cvta_generic_to_shared(smem);
    asm volatile("cp.async.cg.shared.global [%0], [%1], 16;\n" :: "r"(s), "l"(gmem));
}
__device__ __forceinline__ void cp_commit() {
    asm volatile("cp.async.commit_group;\n");
}
template <int N>
__device__ __forceinline__ void cp_wait() {
    asm volatile("cp.async.wait_group %0;\n" :: "n"(N));
}
__device__ __forceinline__ void ldmx4(uint32_t r[4], uint32_t addr) {
    asm volatile("ldmatrix.sync.aligned.m8n8.x4.shared.b16 {%0,%1,%2,%3}, [%4];"
                 : "=r"(r[0]), "=r"(r[1]), "=r"(r[2]), "=r"(r[3]) : "r"(addr));
}
__device__ __forceinline__ void ldmx4t(uint32_t r[4], uint32_t addr) {
    asm volatile("ldmatrix.sync.aligned.m8n8.x4.trans.shared.b16 {%0,%1,%2,%3}, [%4];"
                 : "=r"(r[0]), "=r"(r[1]), "=r"(r[2]), "=r"(r[3]) : "r"(addr));
}
__device__ __forceinline__ void mma16816(float c[4], const uint32_t a[4],
                                         uint32_t b0, uint32_t b1) {
    asm volatile(
        "mma.sync.aligned.m16n8k16.row.col.f32.f16.f16.f32 "
        "{%0,%1,%2,%3}, {%4,%5,%6,%7}, {%8,%9}, {%0,%1,%2,%3};\n"
        : "+f"(c[0]), "+f"(c[1]), "+f"(c[2]), "+f"(c[3])
        : "r"(a[0]), "r"(a[1]), "r"(a[2]), "r"(a[3]), "r"(b0), "r"(b1));
}
__device__ __forceinline__ void mma16816h(uint32_t c[2], const uint32_t a[4],
                                          uint32_t b0, uint32_t b1) {
    asm volatile(
        "mma.sync.aligned.m16n8k16.row.col.f16.f16.f16.f16 "
        "{%0,%1}, {%2,%3,%4,%5}, {%6,%7}, {%0,%1};\n"
        : "+r"(c[0]), "+r"(c[1])
        : "r"(a[0]), "r"(a[1]), "r"(a[2]), "r"(a[3]), "r"(b0), "r"(b1));
}
__device__ __forceinline__ uint32_t s2u(const void* p) {
    return (uint32_t)__cvta_generic_to_shared(p);
}
__device__ __forceinline__ uint32_t pack_h2(float x, float y) {
    __half2 t = __floats2half2_rn(x, y);
    return *(uint32_t*)&t;
}

// ---------------- fp32 -> fp16 convert (vectorized x4) -------------------------
__global__ void cvt4(const float4* __restrict__ in,
                     __half2* __restrict__ out, int n4) {
    int i = blockIdx.x * blockDim.x + threadIdx.x;
    if (i < n4) {
        float4 v = in[i];
        out[2*i]   = __floats2half2_rn(v.x, v.y);
        out[2*i+1] = __floats2half2_rn(v.z, v.w);
    }
}

// ---------------- fp32 [K][N] -> fp16 transposed [N][K], dual-tensor ------------
__global__ void cvt_T2(const float* __restrict__ in0, __half* __restrict__ out0,
                       const float* __restrict__ in1, __half* __restrict__ out1) {
    const int z = blockIdx.z;
    const int N = z ? C_ : N1_;
    if (blockIdx.x * 32 >= N) return;
    const float* in  = z ? in1  : in0;
    __half*      outT = z ? out1 : out0;
    const int K = C_;

    __shared__ float tile[32][33];
    int n0 = blockIdx.x * 32, k0 = blockIdx.y * 32;
    int tx = threadIdx.x & 31, ty = threadIdx.x >> 5;
    #pragma unroll
    for (int i = 0; i < 32; i += 8)
        tile[ty + i][tx] = in[(size_t)(k0 + ty + i)*N + n0 + tx];
    __syncthreads();
    #pragma unroll
    for (int i = 0; i < 32; i += 8)
        outT[(size_t)(n0 + ty + i)*K + k0 + tx] = __float2half_rn(tile[tx][ty + i]);
}

// ---------------- fused raw-mma fp16 GEMM (R12 proven: 3-stage, per-chunk) ------
#define GBM 128
#define GBN 256
#define GBK 64
#define GSTR 72

struct GStage {
    __half A [GBM*GSTR];
    __half Bn[GBN*GSTR];
};
#define G_SMEM_BYTES (3 * (int)sizeof(GStage))

__global__ void __launch_bounds__(256, 1)
gemm_fused(const __half* __restrict__ Ag, const __half* __restrict__ Bt,
           const float* __restrict__ bias, int K, int Nout, int mode,
           __half* __restrict__ k_out, __half* __restrict__ q_out,
           __half* __restrict__ v_out, float* __restrict__ f_out) {
    extern __shared__ __align__(128) char smem_raw[];
    GStage* stg = reinterpret_cast<GStage*>(smem_raw);

    const int tid  = threadIdx.x;
    const int warp = tid >> 5;
    const int lane = tid & 31;
    const int g    = lane >> 2;
    const int tg   = lane & 3;
    const int bm = blockIdx.y * GBM;
    const int bn = blockIdx.x * GBN;
    const int wm = (warp >> 2) * 64;
    const int wn = (warp & 3) * 64;
    const int NIT = K / GBK;

    const int grp = lane >> 3, lr = lane & 7;
    const int rowOffA = ((grp & 1)*8 + lr) * (GSTR*2) + (grp >> 1)*16;
    const int rowOffB = ((grp >> 1)*8 + lr) * (GSTR*2) + (grp & 1)*16;

    auto load_stage = [&](GStage& S, int k0) {
        #pragma unroll
        for (int t = 0; t < 4; t++) {
            int id = tid + 256*t;
            int r = id >> 3, c = (id & 7) * 8;
            cp16(&S.A[r*GSTR + c], &Ag[(size_t)(bm + r)*K + k0 + c]);
        }
        #pragma unroll
        for (int t = 0; t < 8; t++) {
            int id = tid + 256*t;
            int r = id >> 3, c = (id & 7) * 8;
            cp16(&S.Bn[r*GSTR + c], &Bt[(size_t)(bn + r)*K + k0 + c]);
        }
        cp_commit();
    };

    float c[4][8][4];
    #pragma unroll
    for (int i = 0; i < 4; i++)
        #pragma unroll
        for (int j = 0; j < 8; j++)
            c[i][j][0] = c[i][j][1] = c[i][j][2] = c[i][j][3] = 0.f;

    load_stage(stg[0], 0);
    load_stage(stg[1], GBK);

    for (int it = 0; it < NIT; it++) {
        if (it == NIT - 1) cp_wait<0>(); else cp_wait<1>();
        __syncthreads();
        if (it + 2 < NIT) load_stage(stg[(it + 2) % 3], (it + 2) * GBK);

        GStage& S = stg[it % 3];
        const uint32_t baseA = s2u(&S.A[0])  + wm*(GSTR*2) + rowOffA;
        const uint32_t baseB = s2u(&S.Bn[0]) + wn*(GSTR*2) + rowOffB;

        #pragma unroll
        for (int kk = 0; kk < GBK; kk += 16) {
            uint32_t a[4][4], b[4][4];
            #pragma unroll
            for (int mt = 0; mt < 4; mt++)
                ldmx4(a[mt], baseA + mt*16*(GSTR*2) + kk*2);
            #pragma unroll
            for (int nt2 = 0; nt2 < 4; nt2++)
                ldmx4(b[nt2], baseB + nt2*16*(GSTR*2) + kk*2);
            #pragma unroll
            for (int mt = 0; mt < 4; mt++)
                #pragma unroll
                for (int nt = 0; nt < 8; nt++)
                    mma16816(c[mt][nt], a[mt],
                             b[nt >> 1][(nt & 1)*2], b[nt >> 1][(nt & 1)*2 + 1]);
        }
    }

    #pragma unroll
    for (int nt = 0; nt < 8; nt++) {
        const int n = bn + wn + nt*8 + tg*2;
        const float b0f = bias[n], b1f = bias[n + 1];
        if (mode == 0) {
            const int third = n >> 10;
            const int cc = n & 1023;
            const int hh = cc >> 6, dd = cc & 63;
            __half* dst_arr = (third == 0) ? k_out : (third == 1) ? q_out : v_out;
            const float scale = (third == 1) ? (1.0f/32.0f) : 1.0f;
            #pragma unroll
            for (int mt = 0; mt < 4; mt++) {
                #pragma unroll
                for (int half_ = 0; half_ < 2; half_++) {
                    int m = bm + wm + mt*16 + g + half_*8;
                    int bq = m >> 11, tq = m & (T_ - 1);
                    size_t dst = (((size_t)(bq*H_ + hh))*T_ + tq)*D_ + dd;
                    float v0 = (c[mt][nt][half_*2]     + b0f) * scale;
                    float v1 = (c[mt][nt][half_*2 + 1] + b1f) * scale;
                    *(__half2*)&dst_arr[dst] = __floats2half2_rn(v0, v1);
                }
            }
        } else {
            #pragma unroll
            for (int mt = 0; mt < 4; mt++) {
                #pragma unroll
                for (int half_ = 0; half_ < 2; half_++) {
                    int m = bm + wm + mt*16 + g + half_*8;
                    float2 v;
                    v.x = c[mt][nt][half_*2]     + b0f;
                    v.y = c[mt][nt][half_*2 + 1] + b1f;
                    *(float2*)&f_out[(size_t)m*Nout + n] = v;
                }
            }
        }
    }
}

// ---------------- attention v7: ldmatrix K fragments + ldmatrix.trans V ---------
#define KST 72
#define ATT_SQ_ELEMS   (128*KST)
#define ATT_SK_ELEMS   (64*KST)
#define ATT_SV_ELEMS   (64*KST)
#define ATT_SMEM_BYTES ((ATT_SQ_ELEMS + 2*ATT_SK_ELEMS + 2*ATT_SV_ELEMS) * 2)

__global__ void __launch_bounds__(256)
attn_kernel(const __half* __restrict__ Qg,
            const __half* __restrict__ Kg,
            const __half* __restrict__ Vg,
            __half* __restrict__ Og) {
    extern __shared__ __align__(16) __half asmem[];
    __half* sQ = asmem;
    __half* sK = sQ + ATT_SQ_ELEMS;
    __half* sV = sK + 2*ATT_SK_ELEMS;

    const int qtile = gridDim.x - 1 - blockIdx.x;   // heavy tiles first
    const int qb  = qtile * 128;
    const int bh  = blockIdx.y;
    const int b   = bh >> 4, h = bh & 15;
    const int tid = threadIdx.x;
    const int warp = tid >> 5, lane = tid & 31;
    const int g  = lane >> 2;
    const int tg = lane & 3;

    const __half* Qb = Qg + (size_t)bh * T_ * D_;
    const __half* Kb = Kg + (size_t)bh * T_ * D_;
    const __half* Vb = Vg + (size_t)bh * T_ * D_;

    // Q tile -> smem (128x64)
    #pragma unroll
    for (int t = 0; t < 4; t++) {
        int idx = tid + t*256;
        int r = idx >> 3, c = (idx & 7) * 8;
        *(uint4*)&sQ[r*KST + c] = *(const uint4*)&Qb[(size_t)(qb + r)*D_ + c];
    }
    __syncthreads();

    // per-warp persistent Q fragments
    uint32_t qa[4][4];
    {
        int r0 = warp*16 + g;
        #pragma unroll
        for (int kk = 0; kk < 4; kk++) {
            int cb = kk*16 + tg*2;
            qa[kk][0] = *(uint32_t*)&sQ[r0*KST + cb];
            qa[kk][1] = *(uint32_t*)&sQ[(r0+8)*KST + cb];
            qa[kk][2] = *(uint32_t*)&sQ[r0*KST + cb + 8];
            qa[kk][3] = *(uint32_t*)&sQ[(r0+8)*KST + cb + 8];
        }
    }

    float o[8][4];
    #pragma unroll
    for (int i = 0; i < 8; i++) { o[i][0]=o[i][1]=o[i][2]=o[i][3]=0.f; }
    float m0 = -1e30f, m1 = -1e30f, l0 = 0.f, l1 = 0.f;

    const int ntiles = 2*qtile + 2;
    const int vr = tid >> 3, vc0 = (tid & 7) * 8;

    // ldmatrix lane offsets (bytes)
    const int grp = lane >> 3, lr = lane & 7;
    const uint32_t rowOffK = (uint32_t)((((grp >> 1)*8 + lr) * KST + (grp & 1)*8) * 2);
    const uint32_t vlm_off = (uint32_t)(((lane & 15)*KST + ((lane >> 4) << 3)) * 2);

    // preload stage 0: K and V via cp.async (straight layouts)
    {
        #pragma unroll
        for (int t = 0; t < 2; t++) {
            int r = vr + t*32;
            cp16(&sK[r*KST + vc0], &Kb[(size_t)r*D_ + vc0]);
            cp16(&sV[r*KST + vc0], &Vb[(size_t)r*D_ + vc0]);
        }
        cp_commit();
    }

    for (int it = 0; it < ntiles; it++) {
        const int kb = it * 64;
        const int stage = it & 1;
        cp_wait<0>();
        __syncthreads();

        const bool pre = (it + 1 < ntiles);
        if (pre) {
            const int kb2 = kb + 64;
            __half* sKn = sK + (stage ^ 1)*ATT_SK_ELEMS;
            __half* sVn = sV + (stage ^ 1)*ATT_SV_ELEMS;
            #pragma unroll
            for (int t = 0; t < 2; t++) {
                int r = vr + t*32;
                cp16(&sKn[r*KST + vc0], &Kb[(size_t)(kb2 + r)*D_ + vc0]);
                cp16(&sVn[r*KST + vc0], &Vb[(size_t)(kb2 + r)*D_ + vc0]);
            }
            cp_commit();
        }

        if (kb <= qb + warp*16 + 15) {     // per-warp causal skip
            const uint32_t kbase = s2u(sK + stage*ATT_SK_ELEMS) + rowOffK;
            const uint32_t vbase = s2u(sV + stage*ATT_SV_ELEMS) + vlm_off;

            // S = Q @ K^T: K fragments via ldmatrix.x4 (fp16 accum)
            uint32_t sh[8][2];
            #pragma unroll
            for (int nt = 0; nt < 8; nt++) { sh[nt][0] = 0u; sh[nt][1] = 0u; }
            #pragma unroll
            for (int kk = 0; kk < 4; kk++) {
                #pragma unroll
                for (int np = 0; np < 4; np++) {
                    uint32_t bk[4];
                    ldmx4(bk, kbase + (uint32_t)(np*16*(KST*2) + kk*32));
                    mma16816h(sh[2*np],     qa[kk], bk[0], bk[1]);
                    mma16816h(sh[2*np + 1], qa[kk], bk[2], bk[3]);
                }
            }

            // unpack to float
            float s[8][4];
            #pragma unroll
            for (int nt = 0; nt < 8; nt++) {
                float2 lo = __half22float2(*(__half2*)&sh[nt][0]);
                float2 hi = __half22float2(*(__half2*)&sh[nt][1]);
                s[nt][0] = lo.x; s[nt][1] = lo.y;
                s[nt][2] = hi.x; s[nt][3] = hi.y;
            }

            if (kb + 63 > qb + warp*16) {  // diagonal overlap: mask
                int qg0 = qb + warp*16 + g;
                #pragma unroll
                for (int nt = 0; nt < 8; nt++) {
                    int kg = kb + nt*8 + tg*2;
                    if (kg     > qg0    ) s[nt][0] = -1e30f;
                    if (kg + 1 > qg0    ) s[nt][1] = -1e30f;
                    if (kg     > qg0 + 8) s[nt][2] = -1e30f;
                    if (kg + 1 > qg0 + 8) s[nt][3] = -1e30f;
                }
            }

            // online softmax
            float mx0 = -1e30f, mx1 = -1e30f;
            #pragma unroll
            for (int nt = 0; nt < 8; nt++) {
                mx0 = fmaxf(mx0, fmaxf(s[nt][0], s[nt][1]));
                mx1 = fmaxf(mx1, fmaxf(s[nt][2], s[nt][3]));
            }
            #pragma unroll
            for (int off = 1; off < 4; off <<= 1) {
                mx0 = fmaxf(mx0, __shfl_xor_sync(0xffffffffu, mx0, off));
                mx1 = fmaxf(mx1, __shfl_xor_sync(0xffffffffu, mx1, off));
            }
            float nm0 = fmaxf(m0, mx0), nm1 = fmaxf(m1, mx1);
            float a0 = __expf(m0 - nm0), a1 = __expf(m1 - nm1);
            float sum0 = 0.f, sum1 = 0.f;
            #pragma unroll
            for (int nt = 0; nt < 8; nt++) {
                s[nt][0] = __expf(s[nt][0] - nm0);
                s[nt][1] = __expf(s[nt][1] - nm0);
                s[nt][2] = __expf(s[nt][2] - nm1);
                s[nt][3] = __expf(s[nt][3] - nm1);
                sum0 += s[nt][0] + s[nt][1];
                sum1 += s[nt][2] + s[nt][3];
            }
            #pragma unroll
            for (int off = 1; off < 4; off <<= 1) {
                sum0 += __shfl_xor_sync(0xffffffffu, sum0, off);
                sum1 += __shfl_xor_sync(0xffffffffu, sum1, off);
            }
            l0 = l0*a0 + sum0;  l1 = l1*a1 + sum1;
            m0 = nm0;           m1 = nm1;
            #pragma unroll
            for (int nt = 0; nt < 8; nt++) {
                o[nt][0] *= a0; o[nt][1] *= a0; o[nt][2] *= a1; o[nt][3] *= a1;
            }

            // P @ V via ldmatrix.trans on straight V (fp32 accum)
            #pragma unroll
            for (int kt = 0; kt < 4; kt++) {
                uint32_t pa[4];
                pa[0] = pack_h2(s[2*kt  ][0], s[2*kt  ][1]);
                pa[1] = pack_h2(s[2*kt  ][2], s[2*kt  ][3]);
                pa[2] = pack_h2(s[2*kt+1][0], s[2*kt+1][1]);
                pa[3] = pack_h2(s[2*kt+1][2], s[2*kt+1][3]);
                #pragma unroll
                for (int ntp = 0; ntp < 8; ntp += 2) {
                    uint32_t bv[4];
                    ldmx4t(bv, vbase + (uint32_t)((kt*16*KST + ntp*8) * 2));
                    mma16816(o[ntp],     pa, bv[0], bv[1]);
                    mma16816(o[ntp + 1], pa, bv[2], bv[3]);
                }
            }
        }
    }

    // epilogue: O/l -> g_att[b, t, h*64+dd]
    float inv0 = 1.f / l0, inv1 = 1.f / l1;
    int r0 = qb + warp*16 + g;
    #pragma unroll
    for (int nt = 0; nt < 8; nt++) {
        int dd = nt*8 + tg*2;
        __half2 v0 = __floats2half2_rn(o[nt][0]*inv0, o[nt][1]*inv0);
        __half2 v1 = __floats2half2_rn(o[nt][2]*inv1, o[nt][3]*inv1);
        *(__half2*)&Og[((size_t)b*T_ + r0    )*C_ + h*D_ + dd] = v0;
        *(__half2*)&Og[((size_t)b*T_ + r0 + 8)*C_ + h*D_ + dd] = v1;
    }
}

// ---------------- launch --------------------------------------------------------
extern "C" void kernel_launch(void* const* d_in, const int* in_sizes, int n_in,
                              void* d_out, int out_size) {
    const float* x      = (const float*)d_in[0];
    const float* W_kqv  = (const float*)d_in[1];
    const float* b_kqv  = (const float*)d_in[2];
    const float* W_out  = (const float*)d_in[3];
    const float* b_out  = (const float*)d_in[4];
    float*       out    = (float*)d_out;

    __half *p_xh, *p_wkT, *p_woT, *p_q, *p_k, *p_v, *p_att;
    cudaGetSymbolAddress((void**)&p_xh,  g_xh);
    cudaGetSymbolAddress((void**)&p_wkT, g_wkqvT);
    cudaGetSymbolAddress((void**)&p_woT, g_woutT);
    cudaGetSymbolAddress((void**)&p_q,   g_q);
    cudaGetSymbolAddress((void**)&p_k,   g_k);
    cudaGetSymbolAddress((void**)&p_v,   g_v);
    cudaGetSymbolAddress((void**)&p_att, g_att);

    cudaFuncSetAttribute(gemm_fused,
                         cudaFuncAttributeMaxDynamicSharedMemorySize, G_SMEM_BYTES);
    cudaFuncSetAttribute(attn_kernel,
                         cudaFuncAttributeMaxDynamicSharedMemorySize, ATT_SMEM_BYTES);

    // 1) converts
    cvt4<<<(M_*C_/4 + 255)/256, 256>>>((const float4*)x, (__half2*)p_xh, M_*C_/4);
    {
        dim3 gz(N1_/32, C_/32, 2);
        cvt_T2<<<gz, 256>>>(W_kqv, p_wkT, W_out, p_woT);
    }

    // 2) kqv GEMM + fused bias/scatter
    {
        dim3 grid(N1_/GBN, M_/GBM);
        gemm_fused<<<grid, 256, G_SMEM_BYTES>>>(p_xh, p_wkT, b_kqv, C_, N1_, 0,
                                                p_k, p_q, p_v, nullptr);
    }

    // 3) attention
    {
        dim3 grid(T_/128, B_*H_);
        attn_kernel<<<grid, 256, ATT_SMEM_BYTES>>>(p_q, p_k, p_v, p_att);
    }

    // 4) output projection + fused bias -> d_out
    {
        dim3 grid(C_/GBN, M_/GBM);
        gemm_fused<<<grid, 256, G_SMEM_BYTES>>>(p_att, p_woT, b_out, C_, C_, 1,
                                                nullptr, nullptr, nullptr, out);
    }

    (void)in_sizes; (void)n_in; (void)out_size;
}